// round 3
// baseline (speedup 1.0000x reference)
#include <cuda_runtime.h>
#include <cuda_bf16.h>
#include <math.h>

// Problem constants
#define LEVELS   5
#define NNODES   31
#define VV       50000
#define EE       128
#define ENC      128
#define HH       128
#define LBL      104
#define BB       64
#define LL       128
#define BL       (BB*LL)        // 8192
#define G3       384            // 3*H
#define G6       768            // both directions

// ---------------- device scratch (no allocations allowed) ----------------
__device__ float d_P[VV * ENC];          // projected vocab table  (25.6 MB)
__device__ float d_enc[BL * ENC];        // encodes                (4 MB)
__device__ float d_gi[BL * G6];          // input gates, both dirs (25.2 MB)
__device__ float d_whht[2 * G3 * HH];    // Whh transposed, k-major (384 KB)
__device__ float d_pooled[BB * 2 * HH];  // max-pooled GRU outputs

// ---------------- K0: transpose Whh (f & b) to k-major -------------------
__global__ void transpose_whh_kernel(const float* __restrict__ Wf,
                                     const float* __restrict__ Wb) {
    int idx = blockIdx.x * blockDim.x + threadIdx.x;
    const int per = G3 * HH;  // 49152
    if (idx >= 2 * per) return;
    int d = idx / per;
    int r = idx - d * per;
    int j = r / HH;      // gate row 0..383
    int k = r - j * HH;  // hidden col 0..127
    const float* W = d ? Wb : Wf;
    d_whht[d * per + k * G3 + j] = W[j * HH + k];
}

// ---------------- K1: P[v][c] = sum_e emb[v][e] * Wc_w[c][e] -------------
// 128x128 output tile per CTA, 256 threads, 8x8 register tile, K chunked 32.
__global__ void __launch_bounds__(256) proj_table_kernel(
    const float* __restrict__ A,   // emb (V,128)
    const float* __restrict__ Wc)  // Wc_w (128,128)
{
    __shared__ float As[32][132];  // k-major A chunk
    __shared__ float Bs[32][132];  // k-major Wc chunk
    const int row0 = blockIdx.x * 128;
    const int tid = threadIdx.x;
    const int tx = tid & 15;   // col group
    const int ty = tid >> 4;   // row group

    float acc[8][8];
#pragma unroll
    for (int i = 0; i < 8; i++)
#pragma unroll
        for (int j = 0; j < 8; j++) acc[i][j] = 0.f;

    for (int kb = 0; kb < 128; kb += 32) {
#pragma unroll
        for (int i = 0; i < 4; i++) {
            int f = tid + i * 256;    // 0..1023
            int r = f >> 3;           // row/col 0..127
            int kq = f & 7;           // float4 idx within 32 k
            int grow = row0 + r;
            float4 va = (grow < VV)
                ? *(const float4*)&A[(size_t)grow * 128 + kb + kq * 4]
                : make_float4(0.f, 0.f, 0.f, 0.f);
            As[kq * 4 + 0][r] = va.x;
            As[kq * 4 + 1][r] = va.y;
            As[kq * 4 + 2][r] = va.z;
            As[kq * 4 + 3][r] = va.w;
            float4 vb = *(const float4*)&Wc[(size_t)r * 128 + kb + kq * 4];
            Bs[kq * 4 + 0][r] = vb.x;
            Bs[kq * 4 + 1][r] = vb.y;
            Bs[kq * 4 + 2][r] = vb.z;
            Bs[kq * 4 + 3][r] = vb.w;
        }
        __syncthreads();
#pragma unroll
        for (int kk = 0; kk < 32; kk++) {
            float a[8], b[8];
#pragma unroll
            for (int i = 0; i < 8; i++) a[i] = As[kk][ty * 8 + i];
#pragma unroll
            for (int j = 0; j < 8; j++) b[j] = Bs[kk][tx * 8 + j];
#pragma unroll
            for (int i = 0; i < 8; i++)
#pragma unroll
                for (int j = 0; j < 8; j++) acc[i][j] = fmaf(a[i], b[j], acc[i][j]);
        }
        __syncthreads();
    }
#pragma unroll
    for (int i = 0; i < 8; i++) {
        int grow = row0 + ty * 8 + i;
        if (grow < VV) {
            float* dst = &d_P[(size_t)grow * 128 + tx * 8];
            *(float4*)&dst[0] = make_float4(acc[i][0], acc[i][1], acc[i][2], acc[i][3]);
            *(float4*)&dst[4] = make_float4(acc[i][4], acc[i][5], acc[i][6], acc[i][7]);
        }
    }
}

// ---------------- K2: encode = max over nodes of tree-accumulated P -------
// One CTA per (b,l); 128 threads = channels. Heap accumulation in registers.
__global__ void __launch_bounds__(128) encode_kernel(
    const int* __restrict__ tokens,   // (B,L,31)
    const float* __restrict__ Wcb)    // (128,)
{
    const int bl = blockIdx.x;   // 0..8191
    const int c = threadIdx.x;   // 0..127
    __shared__ int tok[NNODES];
    if (c < NNODES) tok[c] = tokens[bl * NNODES + c];
    __syncthreads();

    float v[NNODES];
#pragma unroll
    for (int n = 0; n < NNODES; n++)
        v[n] = d_P[(size_t)tok[n] * 128 + c];

    // bottom-up heap accumulation: parent += left_final + right_final
#pragma unroll
    for (int n = 14; n >= 0; n--)
        v[n] = v[n] + (v[2 * n + 1] + v[2 * n + 2]);

    const float bc = Wcb[c];
    float m = -INFINITY;
#pragma unroll
    for (int n = 0; n < NNODES; n++) {
        int cnt = (n == 0) ? 31 : (n < 3) ? 15 : (n < 7) ? 7 : (n < 15) ? 3 : 1;
        m = fmaxf(m, v[n] + (float)cnt * bc);
    }
    d_enc[bl * 128 + c] = m;
}

// ---------------- K3: gi = enc @ [Wih_f; Wih_b]^T + bias ------------------
// C is (8192 x 768). Tiles 128x128, grid (64, 6).
__global__ void __launch_bounds__(256) gi_kernel(
    const float* __restrict__ Wf, const float* __restrict__ Wb,
    const float* __restrict__ bf, const float* __restrict__ bb)
{
    __shared__ float As[32][132];
    __shared__ float Bs[32][132];
    const int row0 = blockIdx.x * 128;
    const int col0 = blockIdx.y * 128;
    const int tid = threadIdx.x;
    const int tx = tid & 15;
    const int ty = tid >> 4;

    float acc[8][8];
#pragma unroll
    for (int i = 0; i < 8; i++)
#pragma unroll
        for (int j = 0; j < 8; j++) acc[i][j] = 0.f;

    for (int kb = 0; kb < 128; kb += 32) {
#pragma unroll
        for (int i = 0; i < 4; i++) {
            int f = tid + i * 256;
            int r = f >> 3;
            int kq = f & 7;
            float4 va = *(const float4*)&d_enc[(size_t)(row0 + r) * 128 + kb + kq * 4];
            As[kq * 4 + 0][r] = va.x;
            As[kq * 4 + 1][r] = va.y;
            As[kq * 4 + 2][r] = va.z;
            As[kq * 4 + 3][r] = va.w;
            int g = col0 + r;
            const float* W = (g < G3) ? (Wf + (size_t)g * 128) : (Wb + (size_t)(g - G3) * 128);
            float4 vb = *(const float4*)&W[kb + kq * 4];
            Bs[kq * 4 + 0][r] = vb.x;
            Bs[kq * 4 + 1][r] = vb.y;
            Bs[kq * 4 + 2][r] = vb.z;
            Bs[kq * 4 + 3][r] = vb.w;
        }
        __syncthreads();
#pragma unroll
        for (int kk = 0; kk < 32; kk++) {
            float a[8], b[8];
#pragma unroll
            for (int i = 0; i < 8; i++) a[i] = As[kk][ty * 8 + i];
#pragma unroll
            for (int j = 0; j < 8; j++) b[j] = Bs[kk][tx * 8 + j];
#pragma unroll
            for (int i = 0; i < 8; i++)
#pragma unroll
                for (int j = 0; j < 8; j++) acc[i][j] = fmaf(a[i], b[j], acc[i][j]);
        }
        __syncthreads();
    }
#pragma unroll
    for (int i = 0; i < 8; i++) {
        int row = row0 + ty * 8 + i;
#pragma unroll
        for (int j = 0; j < 8; j++) {
            int g = col0 + tx * 8 + j;
            float bias = (g < G3) ? bf[g] : bb[g - G3];
            d_gi[(size_t)row * G6 + g] = acc[i][j] + bias;
        }
    }
}

// ---------------- K4: bidirectional GRU, one CTA per (dir, batch) ---------
// 384 threads; thread j owns gate row j with Whh[j][:] in 128 registers.
// h lives in shared; running max pool folded into the time loop.
__global__ void __launch_bounds__(384, 1) gru_kernel(
    const float* __restrict__ bhf, const float* __restrict__ bhb)
{
    const int dir = blockIdx.x >> 6;   // 0 fwd, 1 bwd
    const int b   = blockIdx.x & 63;
    const int j   = threadIdx.x;       // 0..383

    __shared__ float h_s[HH];
    __shared__ float g_s[G3];

    // Whh row j in registers (k-major transposed layout -> coalesced loads)
    const float* wt = d_whht + (size_t)dir * G3 * HH;
    float w[HH];
#pragma unroll
    for (int k = 0; k < HH; k++) w[k] = wt[k * G3 + j];

    const float bh = dir ? bhb[j] : bhf[j];
    if (j < HH) h_s[j] = 0.f;
    float pmax = -INFINITY;
    const float* gib = d_gi + (size_t)(b * LL) * G6 + dir * G3;
    __syncthreads();

    for (int t = 0; t < LL; t++) {
        const int tt = dir ? (LL - 1 - t) : t;
        const float* girow = gib + (size_t)tt * G6;
        float gir = 0.f, giz = 0.f, gin = 0.f;
        if (j < HH) {  // prefetch input gates; latency hidden under the dot
            gir = girow[j];
            giz = girow[HH + j];
            gin = girow[2 * HH + j];
        }
        float acc0 = bh, acc1 = 0.f;
#pragma unroll
        for (int k = 0; k < HH; k += 8) {
            float4 h0 = *(const float4*)&h_s[k];
            float4 h1 = *(const float4*)&h_s[k + 4];
            acc0 = fmaf(w[k + 0], h0.x, acc0);
            acc1 = fmaf(w[k + 1], h0.y, acc1);
            acc0 = fmaf(w[k + 2], h0.z, acc0);
            acc1 = fmaf(w[k + 3], h0.w, acc1);
            acc0 = fmaf(w[k + 4], h1.x, acc0);
            acc1 = fmaf(w[k + 5], h1.y, acc1);
            acc0 = fmaf(w[k + 6], h1.z, acc0);
            acc1 = fmaf(w[k + 7], h1.w, acc1);
        }
        g_s[j] = acc0 + acc1;
        __syncthreads();
        if (j < HH) {
            float r = 1.f / (1.f + __expf(-(gir + g_s[j])));
            float z = 1.f / (1.f + __expf(-(giz + g_s[HH + j])));
            float n = tanhf(gin + r * g_s[2 * HH + j]);
            float hn = (1.f - z) * n + z * h_s[j];
            h_s[j] = hn;
            pmax = fmaxf(pmax, hn);
        }
        __syncthreads();
    }
    if (j < HH) d_pooled[b * (2 * HH) + dir * HH + j] = pmax;
}

// ---------------- K5: out = pooled @ Wout^T + bout ------------------------
__global__ void __launch_bounds__(128) out_kernel(
    const float* __restrict__ Wout, const float* __restrict__ bout,
    float* __restrict__ out)
{
    const int b = blockIdx.x;
    const int tid = threadIdx.x;
    __shared__ float p_s[2 * HH];
    p_s[tid]      = d_pooled[b * 2 * HH + tid];
    p_s[tid + HH] = d_pooled[b * 2 * HH + HH + tid];
    __syncthreads();
    if (tid < LBL) {
        const float* wr = Wout + (size_t)tid * 2 * HH;
        float acc = bout[tid];
#pragma unroll 8
        for (int k = 0; k < 2 * HH; k++) acc = fmaf(wr[k], p_s[k], acc);
        out[b * LBL + tid] = acc;
    }
}

// ---------------- launch ---------------------------------------------------
extern "C" void kernel_launch(void* const* d_in, const int* in_sizes, int n_in,
                              void* d_out, int out_size) {
    const int*   tokens = (const int*)  d_in[0];
    const float* emb    = (const float*)d_in[1];
    const float* Wc_w   = (const float*)d_in[2];
    const float* Wc_b   = (const float*)d_in[3];
    const float* Wih_f  = (const float*)d_in[4];
    const float* Whh_f  = (const float*)d_in[5];
    const float* bih_f  = (const float*)d_in[6];
    const float* bhh_f  = (const float*)d_in[7];
    const float* Wih_b  = (const float*)d_in[8];
    const float* Whh_b  = (const float*)d_in[9];
    const float* bih_b  = (const float*)d_in[10];
    const float* bhh_b  = (const float*)d_in[11];
    const float* Wout   = (const float*)d_in[12];
    const float* bout   = (const float*)d_in[13];
    float* out = (float*)d_out;

    (void)in_sizes; (void)n_in; (void)out_size;

    transpose_whh_kernel<<<(2 * G3 * HH + 255) / 256, 256>>>(Whh_f, Whh_b);
    proj_table_kernel<<<(VV + 127) / 128, 256>>>(emb, Wc_w);
    encode_kernel<<<BL, 128>>>(tokens, Wc_b);
    gi_kernel<<<dim3(BL / 128, G6 / 128), 256>>>(Wih_f, Wih_b, bih_f, bih_b);
    gru_kernel<<<128, 384>>>(bhh_f, bhh_b);
    out_kernel<<<BB, 128>>>(Wout, bout, out);
}